// round 17
// baseline (speedup 1.0000x reference)
#include <cuda_runtime.h>
#include <cuda_fp16.h>
#include <cstdint>
#include <math.h>

#define NN 50000
#define EE 1600000
#define GG 256
#define HH 128
#define NGB 391   // ceil(50000/128)

// ---------------- scratch ----------------
__device__ int   g_row[NN + 1];
__device__ int   g_col[EE];
__device__ int   g_fill[NN];
__device__ float g_deginv[NN];
__device__ float g_pool[GG * 2 * HH];
// fp16 activation planes (single precision plane — single-term GEMM scheme)
__device__ __align__(16) __half g_x [NN * HH];
__device__ __align__(16) __half g_m [NN * HH];
__device__ __align__(16) __half g_h1[NN * HH];
// 12 weight slots of 128x128, fp16
__device__ __align__(16) __half g_Wh[12 * 16384];

__device__ __forceinline__ uint32_t smem_u32(const void* p) {
    uint32_t a;
    asm("{ .reg .u64 t; cvta.to.shared.u64 t, %1; cvt.u32.u64 %0, t; }" : "=r"(a) : "l"(p));
    return a;
}
__device__ __forceinline__ uint32_t h2_bits(__half2 h) { return *(uint32_t*)&h; }

// ---------------- prep kernels ----------------
// runs at TAIL of each call (globals zero-initialized at load, so call 1 is fine)
__global__ void k_zero2() {
    int b = blockIdx.x;
    if (b < 196) {
        int i = b * 256 + threadIdx.x;
        if (i < NN) g_fill[i] = 0;
    } else {
        int i = (b - 196) * 256 + threadIdx.x;
        if (i < GG * 256) g_pool[i] = 0.f;
    }
}

__global__ void k_count(const int* __restrict__ dst) {
    int e = blockIdx.x * 256 + threadIdx.x;
    if (e < EE) atomicAdd(&g_fill[dst[e]], 1);
}

// x->fp16 plane | W->fp16 (side stream, overlapped with CSR build)
__global__ void k_convxw(const float* __restrict__ x,
                         const float* s0, const float* s1, const float* s2, const float* s3,
                         const float* s4, const float* s5, const float* s6, const float* s7,
                         const float* s8, const float* s9, const float* s10, const float* s11)
{
    int b = blockIdx.x;
    if (b < 6250) {
        int i = (b * 256 + threadIdx.x) * 4;
        float4 v = *(const float4*)(x + i);
        __half2 h01 = __floats2half2_rn(v.x, v.y);
        __half2 h23 = __floats2half2_rn(v.z, v.w);
        *(uint2*)(g_x + i) = make_uint2(h2_bits(h01), h2_bits(h23));
    } else {
        int idx = (b - 6250) * 256 + threadIdx.x;   // 12*16384
        int slot = idx >> 14;
        int w = idx & 16383;
        const float* src;
        switch (slot) {
            case 0: src = s0; break; case 1: src = s1; break;
            case 2: src = s2; break; case 3: src = s3; break;
            case 4: src = s4; break; case 5: src = s5; break;
            case 6: src = s6; break; case 7: src = s7; break;
            case 8: src = s8; break; case 9: src = s9; break;
            case 10: src = s10; break; default: src = s11; break;
        }
        g_Wh[idx] = __float2half_rn(src[w]);
    }
}

__global__ void k_scan() {
    __shared__ int ssum[1024];
    int t = threadIdx.x;
    const int C = (NN + 1023) / 1024;
    int s = t * C;
    int e = s + C; if (e > NN) e = NN;
    int loc = 0;
    for (int i = s; i < e; i++) loc += g_fill[i];
    ssum[t] = loc;
    __syncthreads();
    if (t == 0) {
        int run = 0;
        for (int i = 0; i < 1024; i++) { int v = ssum[i]; ssum[i] = run; run += v; }
        g_row[NN] = run;
    }
    __syncthreads();
    int run = ssum[t];
    for (int i = s; i < e; i++) {
        int c = g_fill[i];
        g_row[i]    = run;
        g_fill[i]   = run;
        g_deginv[i] = 1.0f / fmaxf((float)c, 1.0f);
        run += c;
    }
}
__global__ void k_fillcsr(const int* __restrict__ src, const int* __restrict__ dst) {
    int e = blockIdx.x * blockDim.x + threadIdx.x;
    if (e < EE) {
        int pos = atomicAdd(&g_fill[dst[e]], 1);
        g_col[pos] = src[e];
    }
}

// ---------------- aggregation: 2 nodes/warp, 16 lanes x uint4 ----------------
__global__ __launch_bounds__(256) void k_agg(const __half* __restrict__ in) {
    int tid = threadIdx.x;
    int warp = tid >> 5, lane = tid & 31;
    int l16 = lane & 15;
    int n = blockIdx.x * 16 + warp * 2 + (lane >> 4);
    if (n >= NN) return;
    int s = g_row[n], e = g_row[n + 1];
    float a0 = 0.f, a1 = 0.f, a2 = 0.f, a3 = 0.f;
    float a4 = 0.f, a5 = 0.f, a6 = 0.f, a7 = 0.f;
    const __half* bh = in + l16 * 8;
    #pragma unroll 4
    for (int i = s; i < e; i++) {
        int cc = __ldg(&g_col[i]);
        uint4 u = *(const uint4*)(bh + (size_t)cc * HH);
        float2 f0 = __half22float2(*(__half2*)&u.x);
        float2 f1 = __half22float2(*(__half2*)&u.y);
        float2 f2 = __half22float2(*(__half2*)&u.z);
        float2 f3 = __half22float2(*(__half2*)&u.w);
        a0 += f0.x; a1 += f0.y; a2 += f1.x; a3 += f1.y;
        a4 += f2.x; a5 += f2.y; a6 += f3.x; a7 += f3.y;
    }
    float d = g_deginv[n];
    __half2 hp0 = __floats2half2_rn(a0 * d, a1 * d);
    __half2 hp1 = __floats2half2_rn(a2 * d, a3 * d);
    __half2 hp2 = __floats2half2_rn(a4 * d, a5 * d);
    __half2 hp3 = __floats2half2_rn(a6 * d, a7 * d);
    *(uint4*)(g_m + (size_t)n * HH + l16 * 8) =
        make_uint4(h2_bits(hp0), h2_bits(hp1), h2_bits(hp2), h2_bits(hp3));
}

// ---------------- GEMM (128x128 tile, single-term fp16, 3 CTA/SM) ----------------
// SMEM: A 32KB | Wh 16KB | bias
static constexpr int OFF_A  = 0;
static constexpr int OFF_WH = 32768;
static constexpr int OFF_BI = 49152;
static constexpr int GEMM_SMEM = 49664;

__device__ __forceinline__ uint32_t swz(uint32_t row, uint32_t kbyte) {
    uint32_t col16 = kbyte >> 4;
    uint32_t scol = col16 ^ (row & 7);
    return row * 256 + scol * 16 + (kbyte & 15);
}
__device__ __forceinline__ void ldsm_x4(uint32_t* r, uint32_t addr) {
    asm volatile("ldmatrix.sync.aligned.m8n8.x4.shared.b16 {%0,%1,%2,%3}, [%4];"
                 : "=r"(r[0]), "=r"(r[1]), "=r"(r[2]), "=r"(r[3]) : "r"(addr));
}
__device__ __forceinline__ void ldsm_x4_t(uint32_t* r, uint32_t addr) {
    asm volatile("ldmatrix.sync.aligned.m8n8.x4.trans.shared.b16 {%0,%1,%2,%3}, [%4];"
                 : "=r"(r[0]), "=r"(r[1]), "=r"(r[2]), "=r"(r[3]) : "r"(addr));
}
__device__ __forceinline__ void mma16816(float* c, const uint32_t* a, uint32_t b0, uint32_t b1) {
    asm volatile(
        "mma.sync.aligned.m16n8k16.row.col.f32.f16.f16.f32 "
        "{%0,%1,%2,%3}, {%4,%5,%6,%7}, {%8,%9}, {%0,%1,%2,%3};"
        : "+f"(c[0]), "+f"(c[1]), "+f"(c[2]), "+f"(c[3])
        : "r"(a[0]), "r"(a[1]), "r"(a[2]), "r"(a[3]), "r"(b0), "r"(b1));
}

// one panel, single-term: A @ Wh over K=128 from resident A plane
__device__ __forceinline__ void panel_mma(
    float acc[2][8][4], int slot, char* smem, uint32_t sb,
    int tid, int lane, int wm, int wn)
{
    const __half* wh = g_Wh + slot * 16384;
    uint32_t aRow = (uint32_t)(wm + (lane & 15));
    uint32_t aKadd = (uint32_t)((lane >> 4) * 16);
    uint32_t wRowL = (uint32_t)(lane & 15);
    uint32_t nAdd = (uint32_t)((lane >> 4) * 16);
    int k = tid >> 2, q4 = tid & 3;

    #pragma unroll
    for (int c = 0; c < 2; c++) {
        __syncthreads();   // A visible / prev W consumed
        {
            const uint4* whp = (const uint4*)(wh + (size_t)(c * 64 + k) * 128 + q4 * 32);
            #pragma unroll
            for (int q = 0; q < 4; q++) {
                uint32_t b = (uint32_t)(q4 * 64 + q * 16);
                *(uint4*)(smem + OFF_WH + swz((uint32_t)k, b)) = whp[q];
            }
        }
        __syncthreads();
        #pragma unroll
        for (int ks = 0; ks < 4; ks++) {
            uint32_t kb = (uint32_t)(c * 128 + ks * 32) + aKadd;
            uint32_t ah0[4], ah1[4];
            ldsm_x4(ah0, sb + OFF_A + swz(aRow, kb));
            ldsm_x4(ah1, sb + OFF_A + swz(aRow + 16, kb));
            uint32_t wRow = (uint32_t)(ks * 16) + wRowL;
            #pragma unroll
            for (int bt = 0; bt < 4; bt++) {
                uint32_t nb = (uint32_t)((wn + bt * 16) * 2) + nAdd;
                uint32_t bh[4];
                ldsm_x4_t(bh, sb + OFF_WH + swz(wRow, nb));
                mma16816(acc[0][bt * 2 + 0], ah0, bh[0], bh[1]);
                mma16816(acc[0][bt * 2 + 1], ah0, bh[2], bh[3]);
                mma16816(acc[1][bt * 2 + 0], ah1, bh[0], bh[1]);
                mma16816(acc[1][bt * 2 + 1], ah1, bh[2], bh[3]);
            }
        }
    }
}

// stage direct plane rows into SMEM A (full K=128)
__device__ __forceinline__ void stage_direct(
    const __half* A, int m0, int tid, char* smem)
{
    int r = tid >> 1, half_ = tid & 1;
    int gr = m0 + r; if (gr > NN - 1) gr = NN - 1;
    const uint4* ap = (const uint4*)(A + (size_t)gr * 128 + half_ * 64);
    #pragma unroll
    for (int q = 0; q < 8; q++) {
        uint32_t kb = (uint32_t)(half_ * 128 + q * 16);
        *(uint4*)(smem + OFF_A + swz((uint32_t)r, kb)) = ap[q];
    }
}

// epilogue: bias+relu; plane store and/or pool
__device__ __forceinline__ void epilogue(
    float acc[2][8][4], const float* sB,
    __half* out,
    const int* batch, int poolOff,
    int m0, int lane, int wm, int wn)
{
    int g = lane >> 2, tg = lane & 3;
    #pragma unroll
    for (int mt = 0; mt < 2; mt++) {
        #pragma unroll
        for (int half_ = 0; half_ < 2; half_++) {
            int r = m0 + wm + mt * 16 + g + half_ * 8;
            if (r >= NN) continue;
            int bi = batch ? batch[r] : 0;
            #pragma unroll
            for (int nt = 0; nt < 8; nt++) {
                int col = wn + nt * 8 + tg * 2;
                float vx = fmaxf(acc[mt][nt][half_ * 2 + 0] + sB[col], 0.f);
                float vy = fmaxf(acc[mt][nt][half_ * 2 + 1] + sB[col + 1], 0.f);
                if (out) {
                    __half2 hp = __floats2half2_rn(vx, vy);
                    *(uint32_t*)(out + (size_t)r * 128 + col) = h2_bits(hp);
                }
                if (batch) {
                    float* pp = g_pool + (size_t)bi * 256 + poolOff + col;
                    atomicAdd(pp + 0, vx);
                    atomicAdd(pp + 1, vy);
                }
            }
        }
    }
}

// ---------------- conv1 GEMM: relu(mean@slotL + in@slotR + bias) -> plane ----------------
__global__ __launch_bounds__(256, 3) void k_conv(
    const __half* __restrict__ in,
    int slotL, int slotR, const float* __restrict__ bias,
    __half* __restrict__ out)
{
    extern __shared__ char smem[];
    uint32_t sb = smem_u32(smem);
    int tid = threadIdx.x, lane = tid & 31, wid = tid >> 5;
    int wm = (wid & 3) * 32, wn = (wid >> 2) * 64;
    int m0 = blockIdx.x * 128;
    float* sB = (float*)(smem + OFF_BI);
    if (tid < 128) sB[tid] = bias[tid];

    float acc[2][8][4];
    #pragma unroll
    for (int a = 0; a < 2; a++)
        #pragma unroll
        for (int b = 0; b < 8; b++)
            #pragma unroll
            for (int c = 0; c < 4; c++) acc[a][b][c] = 0.f;

    stage_direct(g_m, m0, tid, smem);
    panel_mma(acc, slotL, smem, sb, tid, lane, wm, wn);
    __syncthreads();
    stage_direct(in, m0, tid, smem);
    panel_mma(acc, slotR, smem, sb, tid, lane, wm, wn);

    epilogue(acc, sB, out, nullptr, 0, m0, lane, wm, wn);
}

// ---------------- fused conv2+JK ----------------
// h2 = relu(mean@sL2 + h1@sR2 + b2)  [kept in SMEM A, never hits global]
// out = relu(h1@sJK1 + h2@sJK2 + bJK) -> optional plane + fused pool
__global__ __launch_bounds__(256, 3) void k_conv2jk(
    const __half* __restrict__ h1,
    int sL2, int sR2, const float* __restrict__ b2,
    int sJK1, int sJK2, const float* __restrict__ bJK,
    __half* __restrict__ out,
    const int* __restrict__ batch, int poolOff)
{
    extern __shared__ char smem[];
    uint32_t sb = smem_u32(smem);
    int tid = threadIdx.x, lane = tid & 31, wid = tid >> 5;
    int wm = (wid & 3) * 32, wn = (wid >> 2) * 64;
    int m0 = blockIdx.x * 128;
    float* sB = (float*)(smem + OFF_BI);
    if (tid < 128) sB[tid] = b2[tid];

    float acc[2][8][4];
    #pragma unroll
    for (int a = 0; a < 2; a++)
        #pragma unroll
        for (int b = 0; b < 8; b++)
            #pragma unroll
            for (int c = 0; c < 4; c++) acc[a][b][c] = 0.f;

    // ---- conv2: mean@Wl2 + h1@Wr2 ----
    stage_direct(g_m, m0, tid, smem);
    panel_mma(acc, sL2, smem, sb, tid, lane, wm, wn);
    __syncthreads();
    stage_direct(h1, m0, tid, smem);
    panel_mma(acc, sR2, smem, sb, tid, lane, wm, wn);

    // ---- h2 = relu(acc + b2); write plane INTO A smem; swap bias ----
    __syncthreads();   // all panel reads of A done before overwrite
    {
        int g = lane >> 2, tg = lane & 3;
        #pragma unroll
        for (int mt = 0; mt < 2; mt++) {
            #pragma unroll
            for (int half_ = 0; half_ < 2; half_++) {
                int rl = wm + mt * 16 + g + half_ * 8;   // local row 0..127
                #pragma unroll
                for (int nt = 0; nt < 8; nt++) {
                    int col = wn + nt * 8 + tg * 2;
                    float vx = fmaxf(acc[mt][nt][half_ * 2 + 0] + sB[col], 0.f);
                    float vy = fmaxf(acc[mt][nt][half_ * 2 + 1] + sB[col + 1], 0.f);
                    __half2 hp = __floats2half2_rn(vx, vy);
                    *(uint32_t*)(smem + OFF_A + swz((uint32_t)rl, (uint32_t)(col * 2))) =
                        h2_bits(hp);
                }
            }
        }
    }
    __syncthreads();
    if (tid < 128) sB[tid] = bJK[tid];

    // ---- JK: h2@WlinB (A already in smem) + h1@WlinT ----
    #pragma unroll
    for (int a = 0; a < 2; a++)
        #pragma unroll
        for (int b = 0; b < 8; b++)
            #pragma unroll
            for (int c = 0; c < 4; c++) acc[a][b][c] = 0.f;

    panel_mma(acc, sJK2, smem, sb, tid, lane, wm, wn);   // h2 @ WlinB
    __syncthreads();
    stage_direct(h1, m0, tid, smem);                     // restage h1
    panel_mma(acc, sJK1, smem, sb, tid, lane, wm, wn);   // h1 @ WlinT

    epilogue(acc, sB, out, batch, poolOff, m0, lane, wm, wn);
}

// ---------------- head ----------------
__global__ void k_head(const float* __restrict__ gamma, const float* __restrict__ beta,
                       const float* __restrict__ rm, const float* __restrict__ rv,
                       const float* __restrict__ W1, const float* __restrict__ b1,
                       const float* __restrict__ W2, const float* __restrict__ b2,
                       float* __restrict__ out)
{
    __shared__ float sg[256];
    __shared__ float s1[128];
    __shared__ float s2[10];
    int gb = blockIdx.x, t = threadIdx.x;
    for (int i = t; i < 256; i += 128) {
        float v = g_pool[gb * 256 + i];
        v = (v - rm[i]) * rsqrtf(rv[i] + 1e-5f) * gamma[i] + beta[i];
        sg[i] = v;
    }
    __syncthreads();
    float acc = b1[t];
    #pragma unroll 8
    for (int k = 0; k < 256; k++) acc += sg[k] * W1[k * 128 + t];
    s1[t] = fmaxf(acc, 0.f);
    __syncthreads();
    if (t < 10) {
        float a = b2[t];
        #pragma unroll 8
        for (int k = 0; k < 128; k++) a += s1[k] * W2[k * 10 + t];
        s2[t] = a;
    }
    __syncthreads();
    if (t == 0) {
        float m = s2[0];
        for (int j = 1; j < 10; j++) m = fmaxf(m, s2[j]);
        float ex[10]; float sum = 0.f;
        for (int j = 0; j < 10; j++) { ex[j] = expf(s2[j] - m); sum += ex[j]; }
        float inv = 1.0f / sum;
        for (int j = 0; j < 10; j++) out[gb * 10 + j] = ex[j] * inv;
    }
}

// ---------------- host launch ----------------
extern "C" void kernel_launch(void* const* d_in, const int* in_sizes, int n_in,
                              void* d_out, int out_size)
{
    const float* x     = (const float*)d_in[0];
    const int*   ei    = (const int*)d_in[1];
    const int*   batch = (const int*)d_in[2];
    int base = (n_in > 3 && in_sizes[3] == 1) ? 4 : 3;

    const float* p[24];
    for (int i = 0; i < 24; i++) p[i] = (const float*)d_in[base + i];
    // b0: 0..7 (Wl1,Wr1,b1,Wl2,Wr2,b2,Wlin,blin); b1: 8..15; bn 16..19; lin1 20,21; lin2 22,23

    const int* src = ei;
    const int* dst = ei + EE;

    void *px, *ph1;
    cudaGetSymbolAddress(&px,  g_x);
    cudaGetSymbolAddress(&ph1, g_h1);
    __half* xh  = (__half*)px;
    __half* h1  = (__half*)ph1;

    // x plane freed after block-0 conv1 -> reuse as block-0 output (hb)
    __half* hb = xh;

    static cudaStream_t sSide = nullptr;
    static cudaEvent_t ev0, ev1;
    if (sSide == nullptr) {
        cudaStreamCreate(&sSide);
        cudaEventCreateWithFlags(&ev0, cudaEventDisableTiming);
        cudaEventCreateWithFlags(&ev1, cudaEventDisableTiming);
        cudaFuncSetAttribute(k_conv,    cudaFuncAttributeMaxDynamicSharedMemorySize, GEMM_SMEM);
        cudaFuncSetAttribute(k_conv2jk, cudaFuncAttributeMaxDynamicSharedMemorySize, GEMM_SMEM);
    }

    // ---- prep: fork conversions onto side stream, CSR chain on main ----
    cudaEventRecord(ev0, 0);
    cudaStreamWaitEvent(sSide, ev0, 0);
    k_convxw<<<6250 + 768, 256, 0, sSide>>>(x,
        p[0], p[1], p[3], p[4], p[6], p[6] + 16384,
        p[8], p[9], p[11], p[12], p[14], p[14] + 16384);
    cudaEventRecord(ev1, sSide);

    k_count<<<6250, 256>>>(dst);
    k_scan<<<1, 1024>>>();
    k_fillcsr<<<6250, 256>>>(src, dst);
    cudaStreamWaitEvent(0, ev1, 0);

    const int AGG_BLOCKS = (NN + 15) / 16;   // 3125

    // ---- block 0 ----
    k_agg<<<AGG_BLOCKS, 256>>>(xh);
    k_conv<<<NGB, 256, GEMM_SMEM>>>(xh, 0, 1, p[2], h1);
    k_agg<<<AGG_BLOCKS, 256>>>(h1);
    k_conv2jk<<<NGB, 256, GEMM_SMEM>>>(h1, 2, 3, p[5], 4, 5, p[7], hb, batch, 0);

    // ---- block 1 ----
    k_agg<<<AGG_BLOCKS, 256>>>(hb);
    k_conv<<<NGB, 256, GEMM_SMEM>>>(hb, 6, 7, p[10], h1);
    k_agg<<<AGG_BLOCKS, 256>>>(h1);
    k_conv2jk<<<NGB, 256, GEMM_SMEM>>>(h1, 8, 9, p[13], 10, 11, p[15],
                                       nullptr, batch, 128);

    // ---- head ----
    k_head<<<GG, 128>>>(p[16], p[17], p[18], p[19], p[20], p[21], p[22], p[23],
                        (float*)d_out);

    // ---- tail: restore zeroed state for the next call ----
    k_zero2<<<452, 256>>>();
}